// round 15
// baseline (speedup 1.0000x reference)
#include <cuda_runtime.h>
#include <cuda_bf16.h>
#include <cuda_fp16.h>
#include <cstdint>

// Problem constants
#define BATCH 2
#define SEQ   2048
#define DM    1024
#define NH    16
#define DK    64
#define M_ROWS (BATCH*SEQ)   // 4096
#define NA (M_ROWS*DM)
#define NW (DM*DM)
#define LOG2E 1.4426950408889634f

// ---------------------------------------------------------------------------
// Helpers (base-sm_103 features: ldmatrix + mma.sync + cp.async)
// ---------------------------------------------------------------------------
__device__ __forceinline__ uint32_t smem_to_u32(const void* p) {
    uint32_t a;
    asm("{ .reg .u64 t; cvta.to.shared.u64 t, %1; cvt.u32.u64 %0, t; }" : "=r"(a) : "l"(p));
    return a;
}
#define SWZ(o) ((uint32_t)(o) ^ ((((uint32_t)(o)) >> 3) & 0x70))

#define STS128(a, r0, r1, r2, r3) \
    asm volatile("st.shared.v4.b32 [%0], {%1, %2, %3, %4};" \
                 :: "r"(a), "r"(r0), "r"(r1), "r"(r2), "r"(r3) : "memory")
#define CP_ASYNC16(dst, src) \
    asm volatile("cp.async.cg.shared.global [%0], [%1], 16;" :: "r"(dst), "l"(src) : "memory")
#define CP_COMMIT() asm volatile("cp.async.commit_group;" ::: "memory")
#define CP_WAIT0()  asm volatile("cp.async.wait_group 0;" ::: "memory")

__device__ __forceinline__ void ldmx4(uint32_t addr, uint32_t r[4]) {
    asm volatile("ldmatrix.sync.aligned.m8n8.x4.shared.b16 {%0,%1,%2,%3}, [%4];"
                 : "=r"(r[0]), "=r"(r[1]), "=r"(r[2]), "=r"(r[3]) : "r"(addr));
}
__device__ __forceinline__ void ldmx4t(uint32_t addr, uint32_t r[4]) {
    asm volatile("ldmatrix.sync.aligned.m8n8.x4.trans.shared.b16 {%0,%1,%2,%3}, [%4];"
                 : "=r"(r[0]), "=r"(r[1]), "=r"(r[2]), "=r"(r[3]) : "r"(addr));
}
__device__ __forceinline__ void mma_fp(float d[4], const uint32_t a[4],
                                       uint32_t b0, uint32_t b1) {
    asm volatile("mma.sync.aligned.m16n8k16.row.col.f32.f16.f16.f32 "
                 "{%0,%1,%2,%3}, {%4,%5,%6,%7}, {%8,%9}, {%0,%1,%2,%3};"
                 : "+f"(d[0]), "+f"(d[1]), "+f"(d[2]), "+f"(d[3])
                 : "r"(a[0]), "r"(a[1]), "r"(a[2]), "r"(a[3]), "r"(b0), "r"(b1));
}

// ---------------------------------------------------------------------------
// Scratch (device globals: allocation-free rule)
// ---------------------------------------------------------------------------
__device__ __half g_ah3[3*NA];                // converted q/k/v inputs (fp16)
__device__ __half g_wh4[4*NW];                // Wq,Wk,Wv,Wo fp16
__device__ __half g_qh[BATCH*NH*SEQ*DK];
__device__ __half g_kh[BATCH*NH*SEQ*DK];      // COMPACTED key index
__device__ __half g_vh[BATCH*NH*SEQ*DK];      // COMPACTED key index
__device__ __half g_xh[NA];
__device__ int    g_perm[BATCH*SEQ];
__device__ int    g_ncnt[BATCH];

// ---------------------------------------------------------------------------
// Unified convert + mask scan in ONE launch.
// y in [0,12): input slice y/4 quarter y%4. y in [12,16): weight y-12.
// y == 16: mask compaction scan (blocks 0..BATCH-1 only; 256 thr x 8 elems).
// ---------------------------------------------------------------------------
__global__ void __launch_bounds__(256)
cvt_all(const float4* __restrict__ q, const float4* __restrict__ k,
        const float4* __restrict__ v,
        const float4* __restrict__ wq, const float4* __restrict__ wk,
        const float4* __restrict__ wv, const float4* __restrict__ wo,
        __half2* __restrict__ in_h, __half2* __restrict__ w_h,
        const int* __restrict__ mask, int* __restrict__ perm,
        int* __restrict__ ncnt)
{
    const int y = blockIdx.y;
    if (y == 16) {
        // Deterministic mask compaction (Hillis-Steele over 256 partial sums).
        __shared__ int sm[256];
        int b = blockIdx.x, t = threadIdx.x;
        if (b >= BATCH) return;
        const int* m = mask + b*SEQ;
        int* pb = perm + b*SEQ;
        int a[8], lsum = 0;
        #pragma unroll
        for (int e = 0; e < 8; e++) {
            pb[8*t + e] = 0;
            a[e] = (m[8*t + e] != 0);
            lsum += a[e];
        }
        sm[t] = lsum;
        __syncthreads();
        #pragma unroll
        for (int off = 1; off < 256; off <<= 1) {
            int vv = (t >= off) ? sm[t-off] : 0;
            __syncthreads();
            sm[t] += vv;
            __syncthreads();
        }
        int pos = sm[t] - lsum;
        #pragma unroll
        for (int e = 0; e < 8; e++) {
            if (a[e]) pb[pos++] = 8*t + e;
        }
        if (t == 255) ncnt[b] = sm[255];
        return;
    }
    const int i = blockIdx.x * blockDim.x + threadIdx.x;   // < NW/4
    const float4* src;
    __half2* h;
    if (y < 12) {
        int z = y >> 2, quad = y & 3;
        src = ((z == 0) ? q : (z == 1) ? k : v) + (size_t)quad*(NW/4);
        h = in_h + (size_t)z*(NA/2) + (size_t)quad*(NW/2);
    } else {
        int z = y - 12;
        src = (z == 0) ? wq : (z == 1) ? wk : (z == 2) ? wv : wo;
        h = w_h + (size_t)z*(NW/2);
    }
    float4 w = src[i];
    h[2*i]   = __floats2half2_rn(w.x, w.y);
    h[2*i+1] = __floats2half2_rn(w.z, w.w);
}

// ---------------------------------------------------------------------------
// fp16 single-pass NT GEMM core (2-buffer, ONE barrier/chunk).
// gather: A-rows indirected through perm.
// BM=BN=128, BK=64, 256 threads (2m x 4n warps), warp tile 64x32.
// ---------------------------------------------------------------------------
#define GB_STRIDE 32768
#define G2_SMEM   65536

__device__ __forceinline__ void g_load(uint32_t sbuf, const __half* Ah,
                                       const __half* Wh, const int* perm,
                                       int m0, int n0, int kc, int tid, int gather)
{
    #pragma unroll
    for (int it = 0; it < 4; it++) {
        int q = tid + it*256; int r = q >> 3, c = q & 7;
        uint32_t so = SWZ(r*128 + c*16);
        int rr = m0 + r;
        int row = gather ? ((rr & ~2047) + __ldg(&perm[rr])) : rr;
        CP_ASYNC16(sbuf + so,         (const void*)(Ah + (size_t)row*DM + kc + c*8));
        CP_ASYNC16(sbuf + 16384 + so, (const void*)(Wh + (size_t)(n0+r)*DM + kc + c*8));
    }
}

__device__ __forceinline__ void gemm_core(
    const __half* __restrict__ Ah, const __half* __restrict__ Wh,
    const int* __restrict__ perm, const float* __restrict__ bias,
    float* __restrict__ Cf, __half* __restrict__ Ch,
    float scale, int mode, int gather, char* smem)
{
    uint32_t sb = smem_to_u32(smem);
    const int tid = threadIdx.x, lane = tid & 31, wid = tid >> 5;
    const int wm = wid & 1, wn = wid >> 1;
    const int m0 = blockIdx.y * 128, n0 = blockIdx.x * 128;

    float acc[4][4][4] = {};

    int a_row[4], b_row[2];
    #pragma unroll
    for (int mt = 0; mt < 4; mt++) a_row[mt] = wm*64 + mt*16 + (lane & 15);
    #pragma unroll
    for (int g = 0; g < 2; g++)
        b_row[g] = wn*32 + g*16 + ((lane >> 4) << 3) + (lane & 7);
    const int a_half = lane >> 4;
    const int b_half = (lane >> 3) & 1;

    g_load(sb, Ah, Wh, perm, m0, n0, 0, tid, gather);
    CP_COMMIT();

    for (int ci = 0; ci < 16; ci++) {
        uint32_t cbuf = sb + (uint32_t)(ci & 1) * GB_STRIDE;
        CP_WAIT0();
        __syncthreads();
        if (ci + 1 < 16) {
            g_load(sb + (uint32_t)((ci+1) & 1) * GB_STRIDE, Ah, Wh, perm,
                   m0, n0, (ci+1)*64, tid, gather);
            CP_COMMIT();
        }
        #pragma unroll
        for (int kk = 0; kk < 4; kk++) {
            uint32_t af[4][4], bh2[2][4];
            #pragma unroll
            for (int mt = 0; mt < 4; mt++) {
                uint32_t off = SWZ(a_row[mt]*128 + (kk*2 + a_half)*16);
                ldmx4(cbuf + off, af[mt]);
            }
            #pragma unroll
            for (int g = 0; g < 2; g++) {
                uint32_t off = SWZ(b_row[g]*128 + (kk*2 + b_half)*16);
                ldmx4(cbuf + 16384 + off, bh2[g]);
            }
            #pragma unroll
            for (int mt = 0; mt < 4; mt++)
                #pragma unroll
                for (int j = 0; j < 4; j++) {
                    int g = j >> 1, pr = (j & 1) * 2;
                    mma_fp(acc[mt][j], af[mt], bh2[g][pr], bh2[g][pr+1]);
                }
        }
    }

    // Epilogue
    #pragma unroll
    for (int mt = 0; mt < 4; mt++) {
        int r0 = m0 + wm*64 + mt*16 + (lane >> 2);
        #pragma unroll
        for (int j = 0; j < 4; j++) {
            int cb = n0 + wn*32 + j*8 + 2*(lane & 3);
            float b0 = __ldg(&bias[cb]), b1 = __ldg(&bias[cb+1]);
            #pragma unroll
            for (int half = 0; half < 2; half++) {
                int m = r0 + half*8;
                float x0 = (acc[mt][j][half*2+0] + b0) * scale;
                float x1 = (acc[mt][j][half*2+1] + b1) * scale;
                if (mode == 0) {
                    float2 o; o.x = x0; o.y = x1;
                    *(float2*)(Cf + (size_t)m*DM + cb) = o;
                } else {
                    int b = m >> 11, s = m & 2047, h = cb >> 6, d = cb & 63;
                    size_t idx = (((size_t)(b*NH + h))*SEQ + s)*DK + d;
                    *(__half2*)(Ch + idx) = __floats2half2_rn(x0, x1);
                }
            }
        }
    }
}

// Q/K/V projections in one launch (z selects). All single-pass.
// K,V (z=1,2) are GATHERED over compacted rows; CTAs beyond ncnt exit.
__global__ void __launch_bounds__(256, 2)
proj3(const __half* __restrict__ A3, const __half* __restrict__ Wh4,
      const int* __restrict__ perm, const int* __restrict__ ncnt,
      const float* __restrict__ bq, const float* __restrict__ bk,
      const float* __restrict__ bv,
      __half* __restrict__ qh, __half* __restrict__ kh, __half* __restrict__ vh)
{
    extern __shared__ char smem[];
    int z = blockIdx.z;
    int gather = (z >= 1);
    if (gather) {
        int m0 = blockIdx.y * 128;
        if ((m0 & 2047) >= __ldg(&ncnt[m0 >> 11])) return;
    }
    const __half* Ah = A3 + (size_t)z*NA;
    const __half* Wh = Wh4 + (size_t)z*NW;
    const float* bias = (z == 0) ? bq : (z == 1) ? bk : bv;
    __half* Ch = (z == 0) ? qh : (z == 1) ? kh : vh;
    float scale = (z == 0) ? 0.125f * LOG2E : 1.0f;
    gemm_core(Ah, Wh, perm, bias, nullptr, Ch, scale, 2, gather, smem);
}

// Output projection (single-pass)
__global__ void __launch_bounds__(256, 2)
gemm_o(const __half* __restrict__ Ah, const __half* __restrict__ Wh,
       const float* __restrict__ bias, float* __restrict__ Cf)
{
    extern __shared__ char smem[];
    gemm_core(Ah, Wh, nullptr, bias, Cf, nullptr, 1.0f, 0, 0, smem);
}

// ---------------------------------------------------------------------------
// Flash attention over PRE-COMPACTED K/V.
// CTA = 128 q-rows, 128 threads; each warp owns 32 q-rows processed as two
// SEQUENTIAL 16-row m-halves (only one s[8][4] live -> no register spills),
// while smem tiles + gmem traffic stay amortized across both halves.
// 64-key tiles, cp.async double buffer (32KB), QK/PV single fp16, exp2 softmax.
// ---------------------------------------------------------------------------
#define AT_K 0
#define AT_V 8192
#define AT_STRIDE 16384
#define AT_SMEM 32768

__device__ __forceinline__ void attn_load_tile(
    uint32_t sbuf, const __half* kh, const __half* vh, int kt, int tid)
{
    #pragma unroll
    for (int it = 0; it < 4; it++) {
        int q = tid + it*128; int r = q >> 3, c = q & 7;
        size_t ro = (size_t)(kt + r) * DK + c*8;
        uint32_t so = SWZ(r*128 + c*16);
        CP_ASYNC16(sbuf + AT_K + so, (const void*)(kh + ro));
        CP_ASYNC16(sbuf + AT_V + so, (const void*)(vh + ro));
    }
}

__global__ void __launch_bounds__(128, 2)
attn_tc(const __half* __restrict__ qhp, const __half* __restrict__ khp,
        const __half* __restrict__ vhp, const int* __restrict__ ncnt,
        __half* __restrict__ xout)
{
    extern __shared__ char dsm[];
    uint32_t sb = smem_to_u32(dsm);

    const int tid = threadIdx.x, lane = tid & 31, w = tid >> 5;
    const int bh = blockIdx.y, b = bh >> 4, h = bh & 15;
    const int q0 = blockIdx.x * 128;

    const int a_half = lane >> 4;
    const int b_rowb = ((lane >> 4) << 3) + (lane & 7);
    const int b_half = (lane >> 3) & 1;
    const int v_krow = ((lane >> 3) & 1)*8 + (lane & 7);
    const int v_dhalf = lane >> 4;

    // ---- Stage Q (128 rows = 16KB across buffer 0), fragments to registers ----
    uint32_t qfh[2][4][4];
    {
        const uint4* ph = (const uint4*)(qhp + ((size_t)bh*SEQ + q0)*DK);
        #pragma unroll
        for (int it = 0; it < 8; it++) {
            int q = tid + it*128; int r = q >> 3, c = q & 7;
            uint32_t so = SWZ(r*128 + c*16);
            uint4 v = ph[r*8 + c];
            STS128(sb + so, v.x, v.y, v.z, v.w);
        }
        __syncthreads();
        #pragma unroll
        for (int mt = 0; mt < 2; mt++) {
            int ar = w*32 + mt*16 + (lane & 15);
            #pragma unroll
            for (int kk = 0; kk < 4; kk++) {
                uint32_t off = SWZ(ar*128 + (kk*2 + a_half)*16);
                ldmx4(sb + off, qfh[mt][kk]);
            }
        }
        __syncthreads();   // buffer 0 free for tile 0
    }

    float acc[2][8][4] = {};
    float mrow[2][2] = {{-1e30f, -1e30f}, {-1e30f, -1e30f}};
    float lrow[2][2] = {};

    const __half* kh = khp + (size_t)bh*SEQ*DK;
    const __half* vh = vhp + (size_t)bh*SEQ*DK;

    const int n = __ldg(&ncnt[b]);
    const int nt = (n + 63) >> 6;

    attn_load_tile(sb, kh, vh, 0, tid);
    CP_COMMIT();

    for (int t = 0; t < nt; t++) {
        uint32_t cb = sb + (uint32_t)(t & 1) * AT_STRIDE;
        CP_WAIT0();
        __syncthreads();
        if (t + 1 < nt) {
            attn_load_tile(sb + (uint32_t)((t+1) & 1) * AT_STRIDE,
                           kh, vh, (t+1)*64, tid);
            CP_COMMIT();
        }

        int rem = n - t*64;

        // ---- SEQUENTIAL m-halves: only one s[8][4] live at a time ----
        #pragma unroll
        for (int mt = 0; mt < 2; mt++) {
            // S = Q K^T over 64 keys (single fp16 pass)
            float s[8][4] = {};
            #pragma unroll
            for (int kk = 0; kk < 4; kk++) {
                #pragma unroll
                for (int g = 0; g < 4; g++) {
                    uint32_t kf[4];
                    uint32_t boff = SWZ((g*16 + b_rowb)*128 + (kk*2 + b_half)*16);
                    ldmx4(cb + AT_K + boff, kf);
                    #pragma unroll
                    for (int pr = 0; pr < 2; pr++)
                        mma_fp(s[g*2 + pr], qfh[mt][kk], kf[pr*2], kf[pr*2+1]);
                }
            }

            // tail mask
            if (rem < 64) {
                int c0 = 2*(lane & 3);
                #pragma unroll
                for (int j = 0; j < 8; j++) {
                    if (j*8 + c0     >= rem) { s[j][0] = -1e9f; s[j][2] = -1e9f; }
                    if (j*8 + c0 + 1 >= rem) { s[j][1] = -1e9f; s[j][3] = -1e9f; }
                }
            }

            // online softmax (exp2 domain)
            float tlo = -1e30f, thi = -1e30f;
            #pragma unroll
            for (int j = 0; j < 8; j++) {
                tlo = fmaxf(tlo, fmaxf(s[j][0], s[j][1]));
                thi = fmaxf(thi, fmaxf(s[j][2], s[j][3]));
            }
            tlo = fmaxf(tlo, __shfl_xor_sync(0xffffffffu, tlo, 1));
            tlo = fmaxf(tlo, __shfl_xor_sync(0xffffffffu, tlo, 2));
            thi = fmaxf(thi, __shfl_xor_sync(0xffffffffu, thi, 1));
            thi = fmaxf(thi, __shfl_xor_sync(0xffffffffu, thi, 2));
            float mnlo = fmaxf(mrow[mt][0], tlo), mnhi = fmaxf(mrow[mt][1], thi);
            float alo = exp2f(mrow[mt][0] - mnlo), ahi = exp2f(mrow[mt][1] - mnhi);
            mrow[mt][0] = mnlo; mrow[mt][1] = mnhi;
            #pragma unroll
            for (int j = 0; j < 8; j++) {
                acc[mt][j][0] *= alo; acc[mt][j][1] *= alo;
                acc[mt][j][2] *= ahi; acc[mt][j][3] *= ahi;
            }

            // fused exp2 + PV over 4 x 16-key chunks
            float slo = 0.f, shi = 0.f;
            #pragma unroll
            for (int ks = 0; ks < 4; ks++) {
                uint32_t pa[4];
                #pragma unroll
                for (int jj = 0; jj < 2; jj++) {
                    int j = 2*ks + jj;
                    float p0 = exp2f(s[j][0] - mnlo), p1 = exp2f(s[j][1] - mnlo);
                    float p2 = exp2f(s[j][2] - mnhi), p3 = exp2f(s[j][3] - mnhi);
                    slo += p0 + p1; shi += p2 + p3;
                    __half2 h0 = __floats2half2_rn(p0, p1);
                    __half2 h1 = __floats2half2_rn(p2, p3);
                    pa[jj*2]   = *(uint32_t*)&h0;
                    pa[jj*2+1] = *(uint32_t*)&h1;
                }
                #pragma unroll
                for (int g = 0; g < 4; g++) {
                    uint32_t vb[4];
                    uint32_t voff = SWZ((ks*16 + v_krow)*128 + (g*2 + v_dhalf)*16);
                    ldmx4t(cb + AT_V + voff, vb);
                    #pragma unroll
                    for (int pr = 0; pr < 2; pr++)
                        mma_fp(acc[mt][g*2+pr], pa, vb[pr*2], vb[pr*2+1]);
                }
            }
            slo += __shfl_xor_sync(0xffffffffu, slo, 1);
            slo += __shfl_xor_sync(0xffffffffu, slo, 2);
            shi += __shfl_xor_sync(0xffffffffu, shi, 1);
            shi += __shfl_xor_sync(0xffffffffu, shi, 2);
            lrow[mt][0] = lrow[mt][0]*alo + slo;
            lrow[mt][1] = lrow[mt][1]*ahi + shi;
        }
    }

    // ---- epilogue: x = acc / l, fp16, layout [b][s][h*64+d] ----
    #pragma unroll
    for (int mt = 0; mt < 2; mt++) {
        float il0 = 1.0f / lrow[mt][0], il1 = 1.0f / lrow[mt][1];
        int r0g = q0 + w*32 + mt*16 + (lane >> 2);
        #pragma unroll
        for (int j = 0; j < 8; j++) {
            int d = j*8 + 2*(lane & 3);
            #pragma unroll
            for (int half = 0; half < 2; half++) {
                int srow = r0g + half*8;
                float il = half ? il1 : il0;
                __half2 o = __floats2half2_rn(acc[mt][j][half*2+0] * il,
                                              acc[mt][j][half*2+1] * il);
                *(__half2*)(xout + ((size_t)b*SEQ + srow)*DM + h*DK + d) = o;
            }
        }
    }
}

// ---------------------------------------------------------------------------
extern "C" void kernel_launch(void* const* d_in, const int* in_sizes, int n_in,
                              void* d_out, int out_size)
{
    const float* query = (const float*)d_in[0];
    const float* key   = (const float*)d_in[1];
    const float* value = (const float*)d_in[2];
    const int*   mask  = (const int*)  d_in[3];
    const float* Wq    = (const float*)d_in[4];
    const float* bq    = (const float*)d_in[5];
    const float* Wk    = (const float*)d_in[6];
    const float* bk    = (const float*)d_in[7];
    const float* Wv    = (const float*)d_in[8];
    const float* bv    = (const float*)d_in[9];
    const float* Wo    = (const float*)d_in[10];
    const float* bo    = (const float*)d_in[11];
    float* out = (float*)d_out;

    __half *ah3, *wh4, *qh, *kh, *vh, *xh;
    int *perm, *ncnt;
    cudaGetSymbolAddress((void**)&ah3, g_ah3);
    cudaGetSymbolAddress((void**)&wh4, g_wh4);
    cudaGetSymbolAddress((void**)&qh, g_qh);
    cudaGetSymbolAddress((void**)&kh, g_kh);
    cudaGetSymbolAddress((void**)&vh, g_vh);
    cudaGetSymbolAddress((void**)&xh, g_xh);
    cudaGetSymbolAddress((void**)&perm, g_perm);
    cudaGetSymbolAddress((void**)&ncnt, g_ncnt);

    cudaFuncSetAttribute(proj3,  cudaFuncAttributeMaxDynamicSharedMemorySize, G2_SMEM);
    cudaFuncSetAttribute(gemm_o, cudaFuncAttributeMaxDynamicSharedMemorySize, G2_SMEM);
    cudaFuncSetAttribute(attn_tc, cudaFuncAttributeMaxDynamicSharedMemorySize, AT_SMEM);

    const int nW4 = NW/4;
    dim3 cgrid(nW4/256, 17);             // 12 input + 4 weight slices + 1 scan row
    dim3 pgrid(DM/128, M_ROWS/128, 3);   // (8, 32, 3)
    dim3 ogrid(DM/128, M_ROWS/128);      // (8, 32)
    dim3 agrid(SEQ/128, BATCH*NH);       // (16, 32)

    cvt_all<<<cgrid, 256>>>((const float4*)query, (const float4*)key,
                            (const float4*)value,
                            (const float4*)Wq, (const float4*)Wk,
                            (const float4*)Wv, (const float4*)Wo,
                            (__half2*)ah3, (__half2*)wh4,
                            mask, perm, ncnt);

    proj3<<<pgrid, 256, G2_SMEM>>>(ah3, wh4, perm, ncnt, bq, bk, bv, qh, kh, vh);

    attn_tc<<<agrid, 128, AT_SMEM>>>(qh, kh, vh, ncnt, xh);

    gemm_o<<<ogrid, 256, G2_SMEM>>>(xh, wh4 + 3*(size_t)NW, bo, out);
}

// round 16
// speedup vs baseline: 1.0263x; 1.0263x over previous
#include <cuda_runtime.h>
#include <cuda_bf16.h>
#include <cuda_fp16.h>
#include <cstdint>

// Problem constants
#define BATCH 2
#define SEQ   2048
#define DM    1024
#define NH    16
#define DK    64
#define M_ROWS (BATCH*SEQ)   // 4096
#define NA (M_ROWS*DM)
#define NW (DM*DM)
#define LOG2E 1.4426950408889634f

// ---------------------------------------------------------------------------
// Helpers (base-sm_103 features: ldmatrix + mma.sync + cp.async)
// ---------------------------------------------------------------------------
__device__ __forceinline__ uint32_t smem_to_u32(const void* p) {
    uint32_t a;
    asm("{ .reg .u64 t; cvta.to.shared.u64 t, %1; cvt.u32.u64 %0, t; }" : "=r"(a) : "l"(p));
    return a;
}
#define SWZ(o) ((uint32_t)(o) ^ ((((uint32_t)(o)) >> 3) & 0x70))

#define STS128(a, r0, r1, r2, r3) \
    asm volatile("st.shared.v4.b32 [%0], {%1, %2, %3, %4};" \
                 :: "r"(a), "r"(r0), "r"(r1), "r"(r2), "r"(r3) : "memory")
#define CP_ASYNC16(dst, src) \
    asm volatile("cp.async.cg.shared.global [%0], [%1], 16;" :: "r"(dst), "l"(src) : "memory")
#define CP_COMMIT() asm volatile("cp.async.commit_group;" ::: "memory")
#define CP_WAIT0()  asm volatile("cp.async.wait_group 0;" ::: "memory")

__device__ __forceinline__ void ldmx4(uint32_t addr, uint32_t r[4]) {
    asm volatile("ldmatrix.sync.aligned.m8n8.x4.shared.b16 {%0,%1,%2,%3}, [%4];"
                 : "=r"(r[0]), "=r"(r[1]), "=r"(r[2]), "=r"(r[3]) : "r"(addr));
}
__device__ __forceinline__ void ldmx4t(uint32_t addr, uint32_t r[4]) {
    asm volatile("ldmatrix.sync.aligned.m8n8.x4.trans.shared.b16 {%0,%1,%2,%3}, [%4];"
                 : "=r"(r[0]), "=r"(r[1]), "=r"(r[2]), "=r"(r[3]) : "r"(addr));
}
__device__ __forceinline__ void mma_fp(float d[4], const uint32_t a[4],
                                       uint32_t b0, uint32_t b1) {
    asm volatile("mma.sync.aligned.m16n8k16.row.col.f32.f16.f16.f32 "
                 "{%0,%1,%2,%3}, {%4,%5,%6,%7}, {%8,%9}, {%0,%1,%2,%3};"
                 : "+f"(d[0]), "+f"(d[1]), "+f"(d[2]), "+f"(d[3])
                 : "r"(a[0]), "r"(a[1]), "r"(a[2]), "r"(a[3]), "r"(b0), "r"(b1));
}

// ---------------------------------------------------------------------------
// Scratch (device globals: allocation-free rule)
// ---------------------------------------------------------------------------
__device__ __half g_ah3[3*NA];                // converted q/k/v inputs (fp16)
__device__ __half g_wh4[4*NW];                // Wq,Wk,Wv,Wo fp16
__device__ __half g_qh[BATCH*NH*SEQ*DK];
__device__ __half g_kh[BATCH*NH*SEQ*DK];      // COMPACTED key index
__device__ __half g_vh[BATCH*NH*SEQ*DK];      // COMPACTED key index
__device__ __half g_xh[NA];
__device__ int    g_perm[BATCH*SEQ];
__device__ int    g_ncnt[BATCH];

// ---------------------------------------------------------------------------
// Unified convert + mask scan in ONE launch.
// y in [0,12): input slice y/4 quarter y%4. y in [12,16): weight y-12.
// y == 16: mask compaction scan (blocks 0..BATCH-1 only; 256 thr x 8 elems).
// ---------------------------------------------------------------------------
__global__ void __launch_bounds__(256)
cvt_all(const float4* __restrict__ q, const float4* __restrict__ k,
        const float4* __restrict__ v,
        const float4* __restrict__ wq, const float4* __restrict__ wk,
        const float4* __restrict__ wv, const float4* __restrict__ wo,
        __half2* __restrict__ in_h, __half2* __restrict__ w_h,
        const int* __restrict__ mask, int* __restrict__ perm,
        int* __restrict__ ncnt)
{
    const int y = blockIdx.y;
    if (y == 16) {
        __shared__ int sm[256];
        int b = blockIdx.x, t = threadIdx.x;
        if (b >= BATCH) return;
        const int* m = mask + b*SEQ;
        int* pb = perm + b*SEQ;
        int a[8], lsum = 0;
        #pragma unroll
        for (int e = 0; e < 8; e++) {
            pb[8*t + e] = 0;
            a[e] = (m[8*t + e] != 0);
            lsum += a[e];
        }
        sm[t] = lsum;
        __syncthreads();
        #pragma unroll
        for (int off = 1; off < 256; off <<= 1) {
            int vv = (t >= off) ? sm[t-off] : 0;
            __syncthreads();
            sm[t] += vv;
            __syncthreads();
        }
        int pos = sm[t] - lsum;
        #pragma unroll
        for (int e = 0; e < 8; e++) {
            if (a[e]) pb[pos++] = 8*t + e;
        }
        if (t == 255) ncnt[b] = sm[255];
        return;
    }
    const int i = blockIdx.x * blockDim.x + threadIdx.x;   // < NW/4
    const float4* src;
    __half2* h;
    if (y < 12) {
        int z = y >> 2, quad = y & 3;
        src = ((z == 0) ? q : (z == 1) ? k : v) + (size_t)quad*(NW/4);
        h = in_h + (size_t)z*(NA/2) + (size_t)quad*(NW/2);
    } else {
        int z = y - 12;
        src = (z == 0) ? wq : (z == 1) ? wk : (z == 2) ? wv : wo;
        h = w_h + (size_t)z*(NW/2);
    }
    float4 w = src[i];
    h[2*i]   = __floats2half2_rn(w.x, w.y);
    h[2*i+1] = __floats2half2_rn(w.z, w.w);
}

// ---------------------------------------------------------------------------
// fp16 single-pass NT GEMM core (2-buffer, ONE barrier/chunk).
// B fragments double-buffered across kk (explicit LDS->MMA decoupling).
// gather: A-rows indirected through perm.
// BM=BN=128, BK=64, 256 threads (2m x 4n warps), warp tile 64x32.
// ---------------------------------------------------------------------------
#define GB_STRIDE 32768
#define G2_SMEM   65536

__device__ __forceinline__ void g_load(uint32_t sbuf, const __half* Ah,
                                       const __half* Wh, const int* perm,
                                       int m0, int n0, int kc, int tid, int gather)
{
    #pragma unroll
    for (int it = 0; it < 4; it++) {
        int q = tid + it*256; int r = q >> 3, c = q & 7;
        uint32_t so = SWZ(r*128 + c*16);
        int rr = m0 + r;
        int row = gather ? ((rr & ~2047) + __ldg(&perm[rr])) : rr;
        CP_ASYNC16(sbuf + so,         (const void*)(Ah + (size_t)row*DM + kc + c*8));
        CP_ASYNC16(sbuf + 16384 + so, (const void*)(Wh + (size_t)(n0+r)*DM + kc + c*8));
    }
}

__device__ __forceinline__ void gemm_core(
    const __half* __restrict__ Ah, const __half* __restrict__ Wh,
    const int* __restrict__ perm, const float* __restrict__ bias,
    float* __restrict__ Cf, __half* __restrict__ Ch,
    float scale, int mode, int gather, char* smem)
{
    uint32_t sb = smem_to_u32(smem);
    const int tid = threadIdx.x, lane = tid & 31, wid = tid >> 5;
    const int wm = wid & 1, wn = wid >> 1;
    const int m0 = blockIdx.y * 128, n0 = blockIdx.x * 128;

    float acc[4][4][4] = {};

    int a_row[4], b_row[2];
    #pragma unroll
    for (int mt = 0; mt < 4; mt++) a_row[mt] = wm*64 + mt*16 + (lane & 15);
    #pragma unroll
    for (int g = 0; g < 2; g++)
        b_row[g] = wn*32 + g*16 + ((lane >> 4) << 3) + (lane & 7);
    const int a_half = lane >> 4;
    const int b_half = (lane >> 3) & 1;

    g_load(sb, Ah, Wh, perm, m0, n0, 0, tid, gather);
    CP_COMMIT();

    for (int ci = 0; ci < 16; ci++) {
        uint32_t cbuf = sb + (uint32_t)(ci & 1) * GB_STRIDE;
        CP_WAIT0();
        __syncthreads();
        if (ci + 1 < 16) {
            g_load(sb + (uint32_t)((ci+1) & 1) * GB_STRIDE, Ah, Wh, perm,
                   m0, n0, (ci+1)*64, tid, gather);
            CP_COMMIT();
        }
        // B fragments double-buffered across kk
        uint32_t bh2[2][2][4];
        #pragma unroll
        for (int g = 0; g < 2; g++) {
            uint32_t off = SWZ(b_row[g]*128 + (0 + b_half)*16);
            ldmx4(cbuf + 16384 + off, bh2[0][g]);
        }
        #pragma unroll
        for (int kk = 0; kk < 4; kk++) {
            uint32_t af[4][4];
            #pragma unroll
            for (int mt = 0; mt < 4; mt++) {
                uint32_t off = SWZ(a_row[mt]*128 + (kk*2 + a_half)*16);
                ldmx4(cbuf + off, af[mt]);
            }
            if (kk < 3) {
                #pragma unroll
                for (int g = 0; g < 2; g++) {
                    uint32_t off = SWZ(b_row[g]*128 + ((kk+1)*2 + b_half)*16);
                    ldmx4(cbuf + 16384 + off, bh2[(kk+1) & 1][g]);
                }
            }
            #pragma unroll
            for (int mt = 0; mt < 4; mt++)
                #pragma unroll
                for (int j = 0; j < 4; j++) {
                    int g = j >> 1, pr = (j & 1) * 2;
                    mma_fp(acc[mt][j], af[mt], bh2[kk & 1][g][pr], bh2[kk & 1][g][pr+1]);
                }
        }
    }

    // Epilogue
    #pragma unroll
    for (int mt = 0; mt < 4; mt++) {
        int r0 = m0 + wm*64 + mt*16 + (lane >> 2);
        #pragma unroll
        for (int j = 0; j < 4; j++) {
            int cb = n0 + wn*32 + j*8 + 2*(lane & 3);
            float b0 = __ldg(&bias[cb]), b1 = __ldg(&bias[cb+1]);
            #pragma unroll
            for (int half = 0; half < 2; half++) {
                int m = r0 + half*8;
                float x0 = (acc[mt][j][half*2+0] + b0) * scale;
                float x1 = (acc[mt][j][half*2+1] + b1) * scale;
                if (mode == 0) {
                    float2 o; o.x = x0; o.y = x1;
                    *(float2*)(Cf + (size_t)m*DM + cb) = o;
                } else {
                    int b = m >> 11, s = m & 2047, h = cb >> 6, d = cb & 63;
                    size_t idx = (((size_t)(b*NH + h))*SEQ + s)*DK + d;
                    *(__half2*)(Ch + idx) = __floats2half2_rn(x0, x1);
                }
            }
        }
    }
}

// Q/K/V projections in one launch (z selects). All single-pass.
// K,V (z=1,2) are GATHERED over compacted rows; CTAs beyond ncnt exit.
__global__ void __launch_bounds__(256, 2)
proj3(const __half* __restrict__ A3, const __half* __restrict__ Wh4,
      const int* __restrict__ perm, const int* __restrict__ ncnt,
      const float* __restrict__ bq, const float* __restrict__ bk,
      const float* __restrict__ bv,
      __half* __restrict__ qh, __half* __restrict__ kh, __half* __restrict__ vh)
{
    extern __shared__ char smem[];
    int z = blockIdx.z;
    int gather = (z >= 1);
    if (gather) {
        int m0 = blockIdx.y * 128;
        if ((m0 & 2047) >= __ldg(&ncnt[m0 >> 11])) return;
    }
    const __half* Ah = A3 + (size_t)z*NA;
    const __half* Wh = Wh4 + (size_t)z*NW;
    const float* bias = (z == 0) ? bq : (z == 1) ? bk : bv;
    __half* Ch = (z == 0) ? qh : (z == 1) ? kh : vh;
    float scale = (z == 0) ? 0.125f * LOG2E : 1.0f;
    gemm_core(Ah, Wh, perm, bias, nullptr, Ch, scale, 2, gather, smem);
}

// Output projection (single-pass)
__global__ void __launch_bounds__(256, 2)
gemm_o(const __half* __restrict__ Ah, const __half* __restrict__ Wh,
       const float* __restrict__ bias, float* __restrict__ Cf)
{
    extern __shared__ char smem[];
    gemm_core(Ah, Wh, nullptr, bias, Cf, nullptr, 1.0f, 0, 0, smem);
}

// ---------------------------------------------------------------------------
// Flash attention over PRE-COMPACTED K/V (R14 version — best known).
// CTA = 128 q-rows, 128 threads (warp = 32 q-rows as TWO 16-row m-halves).
// Each K/V ldmatrix fragment feeds 4 MMAs -> gmem+L1 traffic halved.
// 64-key tiles, cp.async double buffer (32KB), QK/PV single fp16, exp2 softmax.
// ---------------------------------------------------------------------------
#define AT_K 0
#define AT_V 8192
#define AT_STRIDE 16384
#define AT_SMEM 32768

__device__ __forceinline__ void attn_load_tile(
    uint32_t sbuf, const __half* kh, const __half* vh, int kt, int tid)
{
    #pragma unroll
    for (int it = 0; it < 4; it++) {
        int q = tid + it*128; int r = q >> 3, c = q & 7;
        size_t ro = (size_t)(kt + r) * DK + c*8;
        uint32_t so = SWZ(r*128 + c*16);
        CP_ASYNC16(sbuf + AT_K + so, (const void*)(kh + ro));
        CP_ASYNC16(sbuf + AT_V + so, (const void*)(vh + ro));
    }
}

__global__ void __launch_bounds__(128, 2)
attn_tc(const __half* __restrict__ qhp, const __half* __restrict__ khp,
        const __half* __restrict__ vhp, const int* __restrict__ ncnt,
        __half* __restrict__ xout)
{
    extern __shared__ char dsm[];
    uint32_t sb = smem_to_u32(dsm);

    const int tid = threadIdx.x, lane = tid & 31, w = tid >> 5;
    const int bh = blockIdx.y, b = bh >> 4, h = bh & 15;
    const int q0 = blockIdx.x * 128;

    const int a_half = lane >> 4;
    const int b_rowb = ((lane >> 4) << 3) + (lane & 7);
    const int b_half = (lane >> 3) & 1;
    const int v_krow = ((lane >> 3) & 1)*8 + (lane & 7);
    const int v_dhalf = lane >> 4;

    // ---- Stage Q (128 rows = 16KB across buffer 0), fragments to registers ----
    uint32_t qfh[2][4][4];
    {
        const uint4* ph = (const uint4*)(qhp + ((size_t)bh*SEQ + q0)*DK);
        #pragma unroll
        for (int it = 0; it < 8; it++) {
            int q = tid + it*128; int r = q >> 3, c = q & 7;
            uint32_t so = SWZ(r*128 + c*16);
            uint4 v = ph[r*8 + c];
            STS128(sb + so, v.x, v.y, v.z, v.w);
        }
        __syncthreads();
        #pragma unroll
        for (int mt = 0; mt < 2; mt++) {
            int ar = w*32 + mt*16 + (lane & 15);
            #pragma unroll
            for (int kk = 0; kk < 4; kk++) {
                uint32_t off = SWZ(ar*128 + (kk*2 + a_half)*16);
                ldmx4(sb + off, qfh[mt][kk]);
            }
        }
        __syncthreads();   // buffer 0 free for tile 0
    }

    float acc[2][8][4] = {};
    float mrow[2][2] = {{-1e30f, -1e30f}, {-1e30f, -1e30f}};
    float lrow[2][2] = {};

    const __half* kh = khp + (size_t)bh*SEQ*DK;
    const __half* vh = vhp + (size_t)bh*SEQ*DK;

    const int n = __ldg(&ncnt[b]);
    const int nt = (n + 63) >> 6;

    attn_load_tile(sb, kh, vh, 0, tid);
    CP_COMMIT();

    for (int t = 0; t < nt; t++) {
        uint32_t cb = sb + (uint32_t)(t & 1) * AT_STRIDE;
        CP_WAIT0();
        __syncthreads();
        if (t + 1 < nt) {
            attn_load_tile(sb + (uint32_t)((t+1) & 1) * AT_STRIDE,
                           kh, vh, (t+1)*64, tid);
            CP_COMMIT();
        }

        int rem = n - t*64;

        // ---- S = Q K^T over 64 keys, both m-halves per K fragment ----
        float s[2][8][4] = {};
        #pragma unroll
        for (int kk = 0; kk < 4; kk++) {
            #pragma unroll
            for (int g = 0; g < 4; g++) {
                uint32_t kf[4];
                uint32_t boff = SWZ((g*16 + b_rowb)*128 + (kk*2 + b_half)*16);
                ldmx4(cb + AT_K + boff, kf);
                #pragma unroll
                for (int mt = 0; mt < 2; mt++)
                    #pragma unroll
                    for (int pr = 0; pr < 2; pr++)
                        mma_fp(s[mt][g*2 + pr], qfh[mt][kk], kf[pr*2], kf[pr*2+1]);
            }
        }

        // ---- tail mask ----
        if (rem < 64) {
            int c0 = 2*(lane & 3);
            #pragma unroll
            for (int mt = 0; mt < 2; mt++)
                #pragma unroll
                for (int j = 0; j < 8; j++) {
                    if (j*8 + c0     >= rem) { s[mt][j][0] = -1e9f; s[mt][j][2] = -1e9f; }
                    if (j*8 + c0 + 1 >= rem) { s[mt][j][1] = -1e9f; s[mt][j][3] = -1e9f; }
                }
        }

        // ---- online softmax per m-half (exp2 domain) ----
        float mn[2][2], al[2][2];
        #pragma unroll
        for (int mt = 0; mt < 2; mt++) {
            float tlo = -1e30f, thi = -1e30f;
            #pragma unroll
            for (int j = 0; j < 8; j++) {
                tlo = fmaxf(tlo, fmaxf(s[mt][j][0], s[mt][j][1]));
                thi = fmaxf(thi, fmaxf(s[mt][j][2], s[mt][j][3]));
            }
            tlo = fmaxf(tlo, __shfl_xor_sync(0xffffffffu, tlo, 1));
            tlo = fmaxf(tlo, __shfl_xor_sync(0xffffffffu, tlo, 2));
            thi = fmaxf(thi, __shfl_xor_sync(0xffffffffu, thi, 1));
            thi = fmaxf(thi, __shfl_xor_sync(0xffffffffu, thi, 2));
            mn[mt][0] = fmaxf(mrow[mt][0], tlo);
            mn[mt][1] = fmaxf(mrow[mt][1], thi);
            al[mt][0] = exp2f(mrow[mt][0] - mn[mt][0]);
            al[mt][1] = exp2f(mrow[mt][1] - mn[mt][1]);
            mrow[mt][0] = mn[mt][0]; mrow[mt][1] = mn[mt][1];
            #pragma unroll
            for (int j = 0; j < 8; j++) {
                acc[mt][j][0] *= al[mt][0]; acc[mt][j][1] *= al[mt][0];
                acc[mt][j][2] *= al[mt][1]; acc[mt][j][3] *= al[mt][1];
            }
        }

        // ---- fused exp2 + PV; each V fragment feeds both m-halves ----
        float sl[2][2] = {};
        #pragma unroll
        for (int ks = 0; ks < 4; ks++) {
            uint32_t pa[2][4];
            #pragma unroll
            for (int mt = 0; mt < 2; mt++)
                #pragma unroll
                for (int jj = 0; jj < 2; jj++) {
                    int j = 2*ks + jj;
                    float p0 = exp2f(s[mt][j][0] - mn[mt][0]);
                    float p1 = exp2f(s[mt][j][1] - mn[mt][0]);
                    float p2 = exp2f(s[mt][j][2] - mn[mt][1]);
                    float p3 = exp2f(s[mt][j][3] - mn[mt][1]);
                    sl[mt][0] += p0 + p1; sl[mt][1] += p2 + p3;
                    __half2 h0 = __floats2half2_rn(p0, p1);
                    __half2 h1 = __floats2half2_rn(p2, p3);
                    pa[mt][jj*2]   = *(uint32_t*)&h0;
                    pa[mt][jj*2+1] = *(uint32_t*)&h1;
                }
            #pragma unroll
            for (int g = 0; g < 4; g++) {
                uint32_t vb[4];
                uint32_t voff = SWZ((ks*16 + v_krow)*128 + (g*2 + v_dhalf)*16);
                ldmx4t(cb + AT_V + voff, vb);
                #pragma unroll
                for (int mt = 0; mt < 2; mt++)
                    #pragma unroll
                    for (int pr = 0; pr < 2; pr++)
                        mma_fp(acc[mt][g*2+pr], pa[mt], vb[pr*2], vb[pr*2+1]);
            }
        }
        #pragma unroll
        for (int mt = 0; mt < 2; mt++) {
            sl[mt][0] += __shfl_xor_sync(0xffffffffu, sl[mt][0], 1);
            sl[mt][0] += __shfl_xor_sync(0xffffffffu, sl[mt][0], 2);
            sl[mt][1] += __shfl_xor_sync(0xffffffffu, sl[mt][1], 1);
            sl[mt][1] += __shfl_xor_sync(0xffffffffu, sl[mt][1], 2);
            lrow[mt][0] = lrow[mt][0]*al[mt][0] + sl[mt][0];
            lrow[mt][1] = lrow[mt][1]*al[mt][1] + sl[mt][1];
        }
    }

    // ---- epilogue: x = acc / l, fp16, layout [b][s][h*64+d] ----
    #pragma unroll
    for (int mt = 0; mt < 2; mt++) {
        float il0 = 1.0f / lrow[mt][0], il1 = 1.0f / lrow[mt][1];
        int r0g = q0 + w*32 + mt*16 + (lane >> 2);
        #pragma unroll
        for (int j = 0; j < 8; j++) {
            int d = j*8 + 2*(lane & 3);
            #pragma unroll
            for (int half = 0; half < 2; half++) {
                int srow = r0g + half*8;
                float il = half ? il1 : il0;
                __half2 o = __floats2half2_rn(acc[mt][j][half*2+0] * il,
                                              acc[mt][j][half*2+1] * il);
                *(__half2*)(xout + ((size_t)b*SEQ + srow)*DM + h*DK + d) = o;
            }
        }
    }
}

// ---------------------------------------------------------------------------
extern "C" void kernel_launch(void* const* d_in, const int* in_sizes, int n_in,
                              void* d_out, int out_size)
{
    const float* query = (const float*)d_in[0];
    const float* key   = (const float*)d_in[1];
    const float* value = (const float*)d_in[2];
    const int*   mask  = (const int*)  d_in[3];
    const float* Wq    = (const float*)d_in[4];
    const float* bq    = (const float*)d_in[5];
    const float* Wk    = (const float*)d_in[6];
    const float* bk    = (const float*)d_in[7];
    const float* Wv    = (const float*)d_in[8];
    const float* bv    = (const float*)d_in[9];
    const float* Wo    = (const float*)d_in[10];
    const float* bo    = (const float*)d_in[11];
    float* out = (float*)d_out;

    __half *ah3, *wh4, *qh, *kh, *vh, *xh;
    int *perm, *ncnt;
    cudaGetSymbolAddress((void**)&ah3, g_ah3);
    cudaGetSymbolAddress((void**)&wh4, g_wh4);
    cudaGetSymbolAddress((void**)&qh, g_qh);
    cudaGetSymbolAddress((void**)&kh, g_kh);
    cudaGetSymbolAddress((void**)&vh, g_vh);
    cudaGetSymbolAddress((void**)&xh, g_xh);
    cudaGetSymbolAddress((void**)&perm, g_perm);
    cudaGetSymbolAddress((void**)&ncnt, g_ncnt);

    cudaFuncSetAttribute(proj3,  cudaFuncAttributeMaxDynamicSharedMemorySize, G2_SMEM);
    cudaFuncSetAttribute(gemm_o, cudaFuncAttributeMaxDynamicSharedMemorySize, G2_SMEM);
    cudaFuncSetAttribute(attn_tc, cudaFuncAttributeMaxDynamicSharedMemorySize, AT_SMEM);

    const int nW4 = NW/4;
    dim3 cgrid(nW4/256, 17);             // 12 input + 4 weight slices + 1 scan row
    dim3 pgrid(DM/128, M_ROWS/128, 3);   // (8, 32, 3)
    dim3 ogrid(DM/128, M_ROWS/128);      // (8, 32)
    dim3 agrid(SEQ/128, BATCH*NH);       // (16, 32)

    cvt_all<<<cgrid, 256>>>((const float4*)query, (const float4*)key,
                            (const float4*)value,
                            (const float4*)Wq, (const float4*)Wk,
                            (const float4*)Wv, (const float4*)Wo,
                            (__half2*)ah3, (__half2*)wh4,
                            mask, perm, ncnt);

    proj3<<<pgrid, 256, G2_SMEM>>>(ah3, wh4, perm, ncnt, bq, bk, bv, qh, kh, vh);

    attn_tc<<<agrid, 128, AT_SMEM>>>(qh, kh, vh, ncnt, xh);

    gemm_o<<<ogrid, 256, G2_SMEM>>>(xh, wh4 + 3*(size_t)NW, bo, out);
}